// round 8
// baseline (speedup 1.0000x reference)
#include <cuda_runtime.h>
#include <cuda_bf16.h>
#include <stdint.h>

// Problem constants (shapes are fixed by the dataset, but we derive sizes from
// in_sizes at launch for robustness).
#define N_FINE_MAX 200000

// Scratch: inverse map  g_map[unpool_nodes[i]] = i.
// Only entries at positions in unpool_nodes are ever read (edge_src is drawn
// from unpool_nodes), so no init of the rest is needed.
__device__ int g_map[N_FINE_MAX];

__global__ void build_map_kernel(const int* __restrict__ nodes, int n_coarse) {
    int i = blockIdx.x * blockDim.x + threadIdx.x;
    if (i < n_coarse) g_map[nodes[i]] = i;
}

// One warp per edge. Each edge moves 512 floats = 128 float4.
// float4 index layout: idx = lane + 32*j, j=0..3.
//   j=0,1  -> part 0 (straight copy)
//   j=2,3  -> part 1 (complex multiply by conj(connection))
__global__ __launch_bounds__(256) void unpool_kernel(
    const float4* __restrict__ x,        // (N_COARSE * 128) float4  [c,part,k,comp]
    const float2* __restrict__ conn,     // (N_FINE) float2 (cos, sin)
    const int*    __restrict__ edge_src, // (N_FINE)
    const int*    __restrict__ edge_dst, // (N_FINE)
    float4*       __restrict__ out,      // (N_FINE * 128) float4
    int n_fine)
{
    int warp = (int)((blockIdx.x * blockDim.x + threadIdx.x) >> 5);
    int lane = threadIdx.x & 31;
    if (warp >= n_fine) return;

    const int e = warp;
    const int s = __ldg(&edge_src[e]);
    const int d = __ldg(&edge_dst[e]);
    const int c = g_map[s];                 // L2 gather (800 KB table)
    const float2 cs = __ldg(&conn[e]);      // warp-uniform address -> 1 transaction

    const float4* __restrict__ src = x   + (size_t)c * 128;
    float4*       __restrict__ dst = out + (size_t)d * 128;

    // Part 0: x[c,0,:,:] -> out[d,0,:,:]
    {
        float4 v0 = __ldg(&src[lane]);
        float4 v1 = __ldg(&src[lane + 32]);
        dst[lane]      = v0;
        dst[lane + 32] = v1;
    }

    // Part 1: rotate by conj(connection): b = (cos, -sin)
    //   out_re = a_re*cos + a_im*sin
    //   out_im = a_im*cos - a_re*sin
    const float co = cs.x;
    const float si = cs.y;
    #pragma unroll
    for (int j = 2; j < 4; ++j) {
        int idx = lane + 32 * j;
        float4 v = __ldg(&src[idx]);
        float4 r;
        r.x = fmaf(v.x, co,  v.y * si);
        r.y = fmaf(v.y, co, -v.x * si);
        r.z = fmaf(v.z, co,  v.w * si);
        r.w = fmaf(v.w, co, -v.z * si);
        dst[idx] = r;
    }
}

extern "C" void kernel_launch(void* const* d_in, const int* in_sizes, int n_in,
                              void* d_out, int out_size) {
    // metadata order: x, unpool_connection, unpool_nodes, unpool_edges, num_nodes
    const float* x      = (const float*)d_in[0];
    const float* conn   = (const float*)d_in[1];
    const int*   nodes  = (const int*)d_in[2];
    const int*   edges  = (const int*)d_in[3];
    // d_in[4] (num_nodes scalar) unused — derive everything from sizes.

    const int n_coarse = in_sizes[0] / 512;   // x: (n_coarse, 2, 128, 2)
    const int n_fine   = in_sizes[3] / 2;     // edges: (2, n_fine)

    const int* edge_src = edges;
    const int* edge_dst = edges + n_fine;

    // 1) Build inverse unpool map (scatter, ~50K threads)
    {
        int threads = 256;
        int blocks  = (n_coarse + threads - 1) / threads;
        build_map_kernel<<<blocks, threads>>>(nodes, n_coarse);
    }

    // 2) One warp per edge: gather + rotate + scatter
    {
        int threads = 256;                       // 8 warps/block
        int warps_per_block = threads / 32;
        int blocks = (n_fine + warps_per_block - 1) / warps_per_block;
        unpool_kernel<<<blocks, threads>>>(
            (const float4*)x, (const float2*)conn,
            edge_src, edge_dst, (float4*)d_out, n_fine);
    }
}